// round 9
// baseline (speedup 1.0000x reference)
#include <cuda_runtime.h>

// ForwardKinematicsLayer — SMPL 24-joint FK, batch = 262144.
//
// Inputs (metadata order):
//   d_in[0] local_rots : f32 [B, 24, 3, 3]   (B*216 elements)
//   d_in[1] root_pos   : f32 [B, 3]
//   d_in[2] offsets    : f32 [24, 3]
// Output:
//   d_out[0 .. B*72)        global_pos : f32 [B, 24, 3]
//   d_out[B*72 .. B*288)    global_rots: f32 [B, 24, 3, 3]
//
// R6 design: persistent CTAs, grid-stride over 64-item tiles, cp.async
// (LDGSTS) double-buffered loads so DRAM reads stay in flight through the
// compute/store phases. Odd smem strides (217/73) keep every scalar smem
// access bank-conflict-free. 112.6 KB dyn smem -> 2 CTAs/SM; latency hiding
// comes from the async copy engine, not warp count.

#define NJ     24
#define TPB    128
#define ITEMS  64
#define RPAD   217                  // 216 rot floats + 1 pad (odd word stride)
#define PPAD   73                   // 72 pos floats + 1 pad
#define RBUF   (ITEMS * RPAD)       // 13888 words per rot buffer
#define SPW    (ITEMS * 3)          // 192 words per root-pos buffer

static __device__ __forceinline__ int par_of(int j) {
    constexpr int kPar[NJ] = {-1, 0, 0, 0, 1, 2, 3, 4, 5, 6, 7, 8,
                               9, 9, 9, 12, 13, 14, 16, 17, 18, 19, 20, 21};
    return kPar[j];
}

static __device__ __forceinline__ void cp_async4(float* dst, const float* src) {
    unsigned s = (unsigned)__cvta_generic_to_shared(dst);
    asm volatile("cp.async.ca.shared.global [%0], [%1], 4;" :: "r"(s), "l"(src));
}
static __device__ __forceinline__ void cp_commit() {
    asm volatile("cp.async.commit_group;");
}
static __device__ __forceinline__ void cp_wait_all() {
    asm volatile("cp.async.wait_group 0;" ::: "memory");
}

// Issue one tile's loads (non-blocking): 108 rot words + root pos per thread.
static __device__ __forceinline__ void issue_tile_loads(
    const float* __restrict__ lrots, const float* __restrict__ rootp,
    long long tile, float* rbuf, float* spbuf, int tid)
{
    const float* src = lrots + tile * (ITEMS * 216);
#pragma unroll 27
    for (int k = 0; k < (ITEMS * 216) / TPB; ++k) {     // 108 iterations
        int idx  = k * TPB + tid;
        int item = idx / 216;
        int e    = idx - item * 216;
        cp_async4(&rbuf[item * RPAD + e], &src[idx]);
    }
    const float* rp = rootp + tile * (ITEMS * 3);
#pragma unroll
    for (int k = 0; k < 2; ++k) {                        // 192 words total
        int idx = k * TPB + tid;
        if (idx < SPW) cp_async4(&spbuf[idx], &rp[idx]);
    }
}

__global__ void __launch_bounds__(TPB, 2)
fk_kernel(const float* __restrict__ lrots,
          const float* __restrict__ rootp,
          const float* __restrict__ offs,
          float* __restrict__ out,
          int batch, int ntiles)
{
    extern __shared__ float sm[];
    // layout: rbuf0 | rbuf1 | sp0 | sp1
    float* rbuf[2] = { sm, sm + RBUF };
    float* spb [2] = { sm + 2 * RBUF, sm + 2 * RBUF + SPW };
    __shared__ float soffs[NJ * 3];

    const int tid = threadIdx.x;
    if (tid < NJ * 3) soffs[tid] = offs[tid];

    float* out_pos = out;
    float* out_rot = out + (long long)batch * 72;

    // Prologue: start tile 0's loads for this CTA.
    long long t0 = blockIdx.x;
    issue_tile_loads(lrots, rootp, t0, rbuf[0], spb[0], tid);
    cp_commit();

    int s = 0;
    for (long long t = t0; t < ntiles; t += gridDim.x, s ^= 1) {
        cp_wait_all();           // tile t's loads complete (only group pending)
        __syncthreads();         // (A) loads visible; prev stores on buf[s^1] done

        // Kick off next tile's loads into the other buffer (overlaps everything).
        long long nt = t + gridDim.x;
        if (nt < ntiles)
            issue_tile_loads(lrots, rootp, nt, rbuf[s ^ 1], spb[s ^ 1], tid);
        cp_commit();

        float* buf = rbuf[s];
        const long long base_item = t * ITEMS;

        // ---------------- FK chain: threads 0..63, one item each ------------
        float P[NJ][3];
        if (tid < ITEMS) {
            float* my = buf + tid * RPAD;
            P[0][0] = spb[s][tid * 3 + 0];
            P[0][1] = spb[s][tid * 3 + 1];
            P[0][2] = spb[s][tid * 3 + 2];
            // joint 0: global rot == local rot (in place)
#pragma unroll
            for (int j = 1; j < NJ; ++j) {
                const int p = par_of(j);
                float Gp[9], L[9];
#pragma unroll
                for (int c = 0; c < 9; ++c) Gp[c] = my[p * 9 + c];
#pragma unroll
                for (int c = 0; c < 9; ++c) L[c]  = my[j * 9 + c];

                const float o0 = soffs[j * 3 + 0];
                const float o1 = soffs[j * 3 + 1];
                const float o2 = soffs[j * 3 + 2];
#pragma unroll
                for (int i = 0; i < 3; ++i) {
                    P[j][i] = P[p][i]
                            + Gp[i * 3 + 0] * o0
                            + Gp[i * 3 + 1] * o1
                            + Gp[i * 3 + 2] * o2;
                }
#pragma unroll
                for (int i = 0; i < 3; ++i) {
#pragma unroll
                    for (int c = 0; c < 3; ++c) {
                        my[j * 9 + i * 3 + c] =
                              Gp[i * 3 + 0] * L[0 * 3 + c]
                            + Gp[i * 3 + 1] * L[1 * 3 + c]
                            + Gp[i * 3 + 2] * L[2 * 3 + c];
                    }
                }
            }
        }
        __syncthreads();         // (B) global rots ready in smem

        // ---------------- store global rots (coalesced) ---------------------
        {
            const long long rot_base = base_item * 216;
#pragma unroll 27
            for (int k = 0; k < (ITEMS * 216) / TPB; ++k) {
                int idx  = k * TPB + tid;
                int item = idx / 216;
                int e    = idx - item * 216;
                out_rot[rot_base + idx] = buf[item * RPAD + e];
            }
        }
        __syncthreads();         // (C) rot reads done; buf reusable for pos

        if (tid < ITEMS) {
#pragma unroll
            for (int j = 0; j < NJ; ++j) {
#pragma unroll
                for (int c = 0; c < 3; ++c)
                    buf[tid * PPAD + j * 3 + c] = P[j][c];
            }
        }
        __syncthreads();         // (D) pos staged

        // ---------------- store positions (coalesced) -----------------------
        {
            const long long pos_base = base_item * 72;
#pragma unroll
            for (int k = 0; k < (ITEMS * 72) / TPB; ++k) {  // 36 iterations
                int idx  = k * TPB + tid;
                int item = idx / 72;
                int e    = idx - item * 72;
                out_pos[pos_base + idx] = buf[item * PPAD + e];
            }
        }
        // next iteration's barrier (A) orders these pos reads vs. the
        // cp.asyncs that will target this buffer.
    }
}

extern "C" void kernel_launch(void* const* d_in, const int* in_sizes, int n_in,
                              void* d_out, int out_size)
{
    const float* lrots = (const float*)d_in[0];
    const float* rootp = (const float*)d_in[1];
    const float* offs  = (const float*)d_in[2];
    float*       out   = (float*)d_out;

    const int batch  = in_sizes[0] / 216;              // 262144
    const int ntiles = batch / ITEMS;                  // 4096
    const int smem   = (2 * RBUF + 2 * SPW) * (int)sizeof(float); // 112,640 B

    int dev = 0, nsm = 148;
    cudaGetDevice(&dev);
    cudaDeviceGetAttribute(&nsm, cudaDevAttrMultiProcessorCount, dev);
    const int grid = 2 * nsm;                          // 2 persistent CTAs/SM

    cudaFuncSetAttribute(fk_kernel,
                         cudaFuncAttributeMaxDynamicSharedMemorySize, smem);

    fk_kernel<<<grid, TPB, smem>>>(lrots, rootp, offs, out, batch, ntiles);
}

// round 10
// speedup vs baseline: 1.6368x; 1.6368x over previous
#include <cuda_runtime.h>

// ForwardKinematicsLayer — SMPL 24-joint FK, batch = 262144.
//
// Inputs (metadata order):
//   d_in[0] local_rots : f32 [B, 24, 3, 3]   (B*216 elements)
//   d_in[1] root_pos   : f32 [B, 3]
//   d_in[2] offsets    : f32 [24, 3]
// Output:
//   d_out[0 .. B*72)        global_pos : f32 [B, 24, 3]
//   d_out[B*72 .. B*288)    global_rots: f32 [B, 24, 3, 3]
//
// R9 design (evolved from the 106.9us R6 winner):
//  - ITEMS=32 per CTA, 5 CTAs/SM (smem 37.1KB/CTA) -> 20 warps/SM and five
//    independently-phased CTAs so DRAM stays fed through compute windows.
//  - FK chain keeps parent rotations in REGISTERS (ascending-j unroll, ~3
//    parents live) -> no smem round-trip on the critical path.
//  - Positions written straight to a pos-smem region during compute (no
//    72-float register anchor, no extra staging phase). 2 barriers total.
//  - Odd item strides (217 rot / 73 pos) keep every smem access pattern
//    bank-conflict-free in both the coalesced and lane-parallel phases.

#define NJ     24
#define TPB    128
#define ITEMS  32
#define RPAD   217                  // 216 rot floats + 1 pad (odd word stride)
#define PPAD   73                   // 72 pos floats + 1 pad (odd word stride)

static __device__ __forceinline__ int par_of(int j) {
    constexpr int kPar[NJ] = {-1, 0, 0, 0, 1, 2, 3, 4, 5, 6, 7, 8,
                               9, 9, 9, 12, 13, 14, 16, 17, 18, 19, 20, 21};
    return kPar[j];
}

__global__ void __launch_bounds__(TPB, 5)
fk_kernel(const float* __restrict__ lrots,   // [B,24,3,3]
          const float* __restrict__ rootp,   // [B,3]
          const float* __restrict__ offs,    // [24,3]
          float* __restrict__ out,           // [B*72 pos | B*216 rot]
          int batch)
{
    extern __shared__ float sm[];            // rot: ITEMS*RPAD | pos: ITEMS*PPAD
    float* rsm = sm;
    float* psm = sm + ITEMS * RPAD;
    __shared__ float soffs[NJ * 3];

    const int tid = threadIdx.x;
    const long long base_item = (long long)blockIdx.x * ITEMS;

    if (tid < NJ * 3) soffs[tid] = offs[tid];

    const float* in_rot  = lrots + base_item * 216;
    float*       out_pos = out;
    float*       out_rot = out + (long long)batch * 72;

    // ------- Phase 1: coalesced gmem -> smem (local rots + root pos) -------
    // 32*216/128 = 54 fully-unrolled iterations => deep LDG MLP per warp.
#pragma unroll
    for (int k = 0; k < (ITEMS * 216) / TPB; ++k) {
        int idx  = k * TPB + tid;
        int item = idx / 216;
        int e    = idx - item * 216;
        rsm[item * RPAD + e] = in_rot[idx];
    }
    {   // root positions -> pos smem rows [item*PPAD + 0..2]
        const float* rp = rootp + base_item * 3;
        if (tid < ITEMS * 3) {
            int item = tid / 3;
            int c    = tid - item * 3;
            psm[item * PPAD + c] = rp[tid];
        }
    }
    __syncthreads();

    // ------- Phase 2: FK chain, threads 0..31, parents in registers --------
    if (tid < ITEMS) {
        float* my = rsm + tid * RPAD;        // this item's 24 rot slots
        float* mp = psm + tid * PPAD;        // this item's 24 pos slots

        float G[NJ][9];                      // SSA'd by full unroll; ~3 live
        float P[NJ][3];

#pragma unroll
        for (int c = 0; c < 9; ++c) G[0][c] = my[c];    // joint 0: G == L
#pragma unroll
        for (int c = 0; c < 3; ++c) P[0][c] = mp[c];    // root pos (staged)

#pragma unroll
        for (int j = 1; j < NJ; ++j) {
            const int p = par_of(j);

            float L[9];
#pragma unroll
            for (int c = 0; c < 9; ++c) L[c] = my[j * 9 + c];

            const float o0 = soffs[j * 3 + 0];
            const float o1 = soffs[j * 3 + 1];
            const float o2 = soffs[j * 3 + 2];

#pragma unroll
            for (int i = 0; i < 3; ++i) {
                P[j][i] = P[p][i]
                        + G[p][i * 3 + 0] * o0
                        + G[p][i * 3 + 1] * o1
                        + G[p][i * 3 + 2] * o2;
                mp[j * 3 + i] = P[j][i];     // stage pos immediately
            }
#pragma unroll
            for (int i = 0; i < 3; ++i) {
#pragma unroll
                for (int c = 0; c < 3; ++c) {
                    float g = G[p][i * 3 + 0] * L[0 * 3 + c]
                            + G[p][i * 3 + 1] * L[1 * 3 + c]
                            + G[p][i * 3 + 2] * L[2 * 3 + c];
                    G[j][i * 3 + c] = g;
                    my[j * 9 + i * 3 + c] = g;   // stage global rot in place
                }
            }
        }
    }
    __syncthreads();

    // ------- Phase 3: coalesced smem -> gmem (global rots, then pos) -------
    {
        const long long rot_base = base_item * 216;
#pragma unroll
        for (int k = 0; k < (ITEMS * 216) / TPB; ++k) {   // 54 iterations
            int idx  = k * TPB + tid;
            int item = idx / 216;
            int e    = idx - item * 216;
            out_rot[rot_base + idx] = rsm[item * RPAD + e];
        }
        const long long pos_base = base_item * 72;
#pragma unroll
        for (int k = 0; k < (ITEMS * 72) / TPB; ++k) {    // 18 iterations
            int idx  = k * TPB + tid;
            int item = idx / 72;
            int e    = idx - item * 72;
            out_pos[pos_base + idx] = psm[item * PPAD + e];
        }
    }
}

extern "C" void kernel_launch(void* const* d_in, const int* in_sizes, int n_in,
                              void* d_out, int out_size)
{
    const float* lrots = (const float*)d_in[0];
    const float* rootp = (const float*)d_in[1];
    const float* offs  = (const float*)d_in[2];
    float*       out   = (float*)d_out;

    const int batch = in_sizes[0] / 216;                 // 262144
    const int grid  = batch / ITEMS;                     // 8192 blocks
    const int smem  = (ITEMS * RPAD + ITEMS * PPAD) * (int)sizeof(float); // 37,120 B

    cudaFuncSetAttribute(fk_kernel,
                         cudaFuncAttributeMaxDynamicSharedMemorySize, smem);

    fk_kernel<<<grid, TPB, smem>>>(lrots, rootp, offs, out, batch);
}

// round 11
// speedup vs baseline: 1.6639x; 1.0166x over previous
#include <cuda_runtime.h>

// ForwardKinematicsLayer — SMPL 24-joint FK, batch = 262144.
//
// Inputs (metadata order):
//   d_in[0] local_rots : f32 [B, 24, 3, 3]   (B*216 elements)
//   d_in[1] root_pos   : f32 [B, 3]
//   d_in[2] offsets    : f32 [24, 3]
// Output:
//   d_out[0 .. B*72)        global_pos : f32 [B, 24, 3]
//   d_out[B*72 .. B*288)    global_rots: f32 [B, 24, 3, 3]
//
// R9 design (evolved from the 106.9us R6 winner):
//  - ITEMS=32 per CTA, 5 CTAs/SM (smem 37.1KB/CTA) -> 20 warps/SM and five
//    independently-phased CTAs so DRAM stays fed through compute windows.
//  - FK chain keeps parent rotations in REGISTERS (ascending-j unroll, ~3
//    parents live) -> no smem round-trip on the critical path.
//  - Positions written straight to a pos-smem region during compute (no
//    72-float register anchor, no extra staging phase). 2 barriers total.
//  - Odd item strides (217 rot / 73 pos) keep every smem access pattern
//    bank-conflict-free in both the coalesced and lane-parallel phases.

#define NJ     24
#define TPB    128
#define ITEMS  32
#define RPAD   217                  // 216 rot floats + 1 pad (odd word stride)
#define PPAD   73                   // 72 pos floats + 1 pad (odd word stride)

static __device__ __forceinline__ int par_of(int j) {
    constexpr int kPar[NJ] = {-1, 0, 0, 0, 1, 2, 3, 4, 5, 6, 7, 8,
                               9, 9, 9, 12, 13, 14, 16, 17, 18, 19, 20, 21};
    return kPar[j];
}

__global__ void __launch_bounds__(TPB, 5)
fk_kernel(const float* __restrict__ lrots,   // [B,24,3,3]
          const float* __restrict__ rootp,   // [B,3]
          const float* __restrict__ offs,    // [24,3]
          float* __restrict__ out,           // [B*72 pos | B*216 rot]
          int batch)
{
    extern __shared__ float sm[];            // rot: ITEMS*RPAD | pos: ITEMS*PPAD
    float* rsm = sm;
    float* psm = sm + ITEMS * RPAD;
    __shared__ float soffs[NJ * 3];

    const int tid = threadIdx.x;
    const long long base_item = (long long)blockIdx.x * ITEMS;

    if (tid < NJ * 3) soffs[tid] = offs[tid];

    const float* in_rot  = lrots + base_item * 216;
    float*       out_pos = out;
    float*       out_rot = out + (long long)batch * 72;

    // ------- Phase 1: coalesced gmem -> smem (local rots + root pos) -------
    // 32*216/128 = 54 fully-unrolled iterations => deep LDG MLP per warp.
#pragma unroll
    for (int k = 0; k < (ITEMS * 216) / TPB; ++k) {
        int idx  = k * TPB + tid;
        int item = idx / 216;
        int e    = idx - item * 216;
        rsm[item * RPAD + e] = in_rot[idx];
    }
    {   // root positions -> pos smem rows [item*PPAD + 0..2]
        const float* rp = rootp + base_item * 3;
        if (tid < ITEMS * 3) {
            int item = tid / 3;
            int c    = tid - item * 3;
            psm[item * PPAD + c] = rp[tid];
        }
    }
    __syncthreads();

    // ------- Phase 2: FK chain, threads 0..31, parents in registers --------
    if (tid < ITEMS) {
        float* my = rsm + tid * RPAD;        // this item's 24 rot slots
        float* mp = psm + tid * PPAD;        // this item's 24 pos slots

        float G[NJ][9];                      // SSA'd by full unroll; ~3 live
        float P[NJ][3];

#pragma unroll
        for (int c = 0; c < 9; ++c) G[0][c] = my[c];    // joint 0: G == L
#pragma unroll
        for (int c = 0; c < 3; ++c) P[0][c] = mp[c];    // root pos (staged)

#pragma unroll
        for (int j = 1; j < NJ; ++j) {
            const int p = par_of(j);

            float L[9];
#pragma unroll
            for (int c = 0; c < 9; ++c) L[c] = my[j * 9 + c];

            const float o0 = soffs[j * 3 + 0];
            const float o1 = soffs[j * 3 + 1];
            const float o2 = soffs[j * 3 + 2];

#pragma unroll
            for (int i = 0; i < 3; ++i) {
                P[j][i] = P[p][i]
                        + G[p][i * 3 + 0] * o0
                        + G[p][i * 3 + 1] * o1
                        + G[p][i * 3 + 2] * o2;
                mp[j * 3 + i] = P[j][i];     // stage pos immediately
            }
#pragma unroll
            for (int i = 0; i < 3; ++i) {
#pragma unroll
                for (int c = 0; c < 3; ++c) {
                    float g = G[p][i * 3 + 0] * L[0 * 3 + c]
                            + G[p][i * 3 + 1] * L[1 * 3 + c]
                            + G[p][i * 3 + 2] * L[2 * 3 + c];
                    G[j][i * 3 + c] = g;
                    my[j * 9 + i * 3 + c] = g;   // stage global rot in place
                }
            }
        }
    }
    __syncthreads();

    // ------- Phase 3: coalesced smem -> gmem (global rots, then pos) -------
    {
        const long long rot_base = base_item * 216;
#pragma unroll
        for (int k = 0; k < (ITEMS * 216) / TPB; ++k) {   // 54 iterations
            int idx  = k * TPB + tid;
            int item = idx / 216;
            int e    = idx - item * 216;
            out_rot[rot_base + idx] = rsm[item * RPAD + e];
        }
        const long long pos_base = base_item * 72;
#pragma unroll
        for (int k = 0; k < (ITEMS * 72) / TPB; ++k) {    // 18 iterations
            int idx  = k * TPB + tid;
            int item = idx / 72;
            int e    = idx - item * 72;
            out_pos[pos_base + idx] = psm[item * PPAD + e];
        }
    }
}

extern "C" void kernel_launch(void* const* d_in, const int* in_sizes, int n_in,
                              void* d_out, int out_size)
{
    const float* lrots = (const float*)d_in[0];
    const float* rootp = (const float*)d_in[1];
    const float* offs  = (const float*)d_in[2];
    float*       out   = (float*)d_out;

    const int batch = in_sizes[0] / 216;                 // 262144
    const int grid  = batch / ITEMS;                     // 8192 blocks
    const int smem  = (ITEMS * RPAD + ITEMS * PPAD) * (int)sizeof(float); // 37,120 B

    cudaFuncSetAttribute(fk_kernel,
                         cudaFuncAttributeMaxDynamicSharedMemorySize, smem);

    fk_kernel<<<grid, TPB, smem>>>(lrots, rootp, offs, out, batch);
}